// round 14
// baseline (speedup 1.0000x reference)
#include <cuda_runtime.h>
#include <cstdint>
#include <cstddef>

// ---------------- problem constants ----------------
#define BATCH   16384
#define SEQ     15
#define DIM     512
#define UNITS   32
#define NQK     64
#define TOTROWS (BATCH * SEQ)          // 245760

// ---------------- kernel A (GEMM) tiling ----------------
#define A_THREADS 256
#define A_WARPS   8
#define WARP_ROWS 16
#define A_ROWS    (A_WARPS * WARP_ROWS)      // 128 rows per CTA
#define A_GRID    (TOTROWS / A_ROWS)         // 1920
#define KCHUNK    32
#define NCHUNKS   (DIM / KCHUNK)             // 16
#define WSTAGE    3
#define WS_ST     36                          // per-warp stage row stride
#define STAGEF    (WARP_ROWS * WS_ST)         // 576 floats per stage
#define WARPF     (WSTAGE * STAGEF)           // 1728 floats per warp
#define A_SMEM_FLOATS (A_WARPS * WARPF)       // 13824
#define A_SMEM_BYTES  (A_SMEM_FLOATS * 4)     // 55296 -> 3 CTAs/SM

// ---------------- kernel B (attention) ----------------
#define B_WARPS   4
#define B_THREADS 128
#define B_GRID    (BATCH / B_WARPS)    // 4096
#define QK_ST     68
#define EAT_ST    16

// ---------------- scratch ----------------
__device__ float  g_qk[(size_t)TOTROWS * NQK];            // 62.9 MB
__device__ float2 g_Wf[NCHUNKS * 4 * 8 * 32];             // fragment-ordered W, 128 KB

// ---------------- helpers ----------------
__device__ __forceinline__ void cp16(void* dst, const void* src) {
    uint32_t d = (uint32_t)__cvta_generic_to_shared(dst);
    asm volatile("cp.async.cg.shared.global [%0], [%1], 16;" :: "r"(d), "l"(src));
}
#define CP_COMMIT() asm volatile("cp.async.commit_group;")
#define CP_WAIT1()  asm volatile("cp.async.wait_group 1;")
#define CP_WAIT0()  asm volatile("cp.async.wait_group 0;")

__device__ __forceinline__ void mma_tf32(float* c,
                                         uint32_t a0, uint32_t a1, uint32_t a2, uint32_t a3,
                                         uint32_t b0, uint32_t b1) {
    asm volatile(
        "mma.sync.aligned.m16n8k8.row.col.f32.tf32.tf32.f32 "
        "{%0,%1,%2,%3}, {%4,%5,%6,%7}, {%8,%9}, {%0,%1,%2,%3};"
        : "+f"(c[0]), "+f"(c[1]), "+f"(c[2]), "+f"(c[3])
        : "r"(a0), "r"(a1), "r"(a2), "r"(a3), "r"(b0), "r"(b1));
}

__device__ __forceinline__ float rcp_fast(float v) {
    float r;
    asm("rcp.approx.f32 %0, %1;" : "=f"(r) : "f"(v));
    return r;
}

// ================= kernel 0: W -> fragment-ordered layout =================
// g_Wf[((c*4 + k8)*8 + nt)*32 + lane] = { W[k][n], W[k+4][n] },
// n = nt*8 + (lane>>2), k = c*32 + k8*8 + (lane&3)  (validated in R13).
__global__ void prep_wf_kernel(const float* __restrict__ Wt,
                               const float* __restrict__ Wx) {
    int idx  = blockIdx.x * 256 + threadIdx.x;   // 0..16383
    int lane = idx & 31;
    int nt   = (idx >> 5) & 7;
    int k8   = (idx >> 8) & 3;
    int c    = idx >> 10;
    int n    = nt * 8 + (lane >> 2);
    int k    = c * KCHUNK + k8 * 8 + (lane & 3);
    float v0 = (n < UNITS) ? Wt[k * UNITS + n]       : Wx[k * UNITS + (n - UNITS)];
    float v1 = (n < UNITS) ? Wt[(k + 4) * UNITS + n] : Wx[(k + 4) * UNITS + (n - UNITS)];
    g_Wf[idx] = make_float2(v0, v1);
}

// ================= kernel A: qk = x @ [Wt|Wx] + bh =================
// WARP-AUTONOMOUS: each warp owns 16 rows + a private 3-stage cp.async ring.
// Zero __syncthreads in the mainloop; warps free-run like attn's.
__global__ __launch_bounds__(A_THREADS, 3)
void gemm_qk_kernel(const float* __restrict__ x,
                    const float* __restrict__ bh) {
    extern __shared__ float sm[];

    const int tid  = threadIdx.x;
    const int lane = tid & 31;
    const int w    = tid >> 5;
    float* ws = sm + w * WARPF;                       // this warp's ring
    const long long rowbase = (long long)blockIdx.x * A_ROWS + (long long)w * WARP_ROWS;

    // stage one 16-row x 32-k chunk into this warp's ring (4 cp16 per lane)
    auto issue = [&](int q) {
        float* st = ws + (q % WSTAGE) * STAGEF;
        const int kc = q * KCHUNK;
        #pragma unroll
        for (int i = 0; i < 4; i++) {
            int f   = lane + 32 * i;      // 0..127 float4 slots
            int row = f >> 3;             // 0..15
            int c4  = f & 7;              // 0..7
            cp16(st + row * WS_ST + c4 * 4,
                 x + (rowbase + row) * DIM + kc + c4 * 4);
        }
        CP_COMMIT();
    };

    issue(0);
    issue(1);

    float acc[8][4];
    #pragma unroll
    for (int n = 0; n < 8; n++)
        #pragma unroll
        for (int q = 0; q < 4; q++) acc[n][q] = 0.f;

    const int g  = lane >> 2;
    const int tg = lane & 3;

    for (int c = 0; c < NCHUNKS; c++) {
        if (c == NCHUNKS - 1) { CP_WAIT0(); } else { CP_WAIT1(); }
        __syncwarp();          // chunk c visible warp-wide; all lanes past compute(c-1)

        if (c + 2 < NCHUNKS) issue(c + 2);   // overwrites stage (c-1)%3 (safe: post-syncwarp)

        const float* st = ws + (c % WSTAGE) * STAGEF;
        const float2* wf = g_Wf + (size_t)(c * 4) * 8 * 32 + lane;

        #pragma unroll
        for (int k8 = 0; k8 < 4; k8++) {
            const int kb = k8 * 8;
            const float* ar = st + g * WS_ST + kb + tg;
            uint32_t a0 = __float_as_uint(ar[0]);
            uint32_t a1 = __float_as_uint(ar[8 * WS_ST]);
            uint32_t a2 = __float_as_uint(ar[4]);
            uint32_t a3 = __float_as_uint(ar[8 * WS_ST + 4]);
            const float2* wk = wf + (size_t)k8 * 8 * 32;
            float2 b[8];
            #pragma unroll
            for (int nt = 0; nt < 8; nt++) b[nt] = __ldg(wk + nt * 32);
            #pragma unroll
            for (int nt = 0; nt < 8; nt++) {
                mma_tf32(acc[nt], a0, a1, a2, a3,
                         __float_as_uint(b[nt].x), __float_as_uint(b[nt].y));
            }
        }
    }

    // epilogue: write this warp's 16 rows (+bh on cols < 32)
    const int r0 = g;
    const int r1 = g + 8;
    #pragma unroll
    for (int nt = 0; nt < 8; nt++) {
        int cc = nt * 8 + tg * 2;
        float b0 = (cc     < UNITS) ? __ldg(bh + cc)     : 0.f;
        float b1 = (cc + 1 < UNITS) ? __ldg(bh + cc + 1) : 0.f;
        float2 v0 = make_float2(acc[nt][0] + b0, acc[nt][1] + b1);
        float2 v1 = make_float2(acc[nt][2] + b0, acc[nt][3] + b1);
        *(float2*)(g_qk + (size_t)(rowbase + r0) * NQK + cc) = v0;
        *(float2*)(g_qk + (size_t)(rowbase + r1) * NQK + cc) = v1;
    }
}

// ================= kernel B: e/softmax/AV (round-6 control, 200us) =================
__global__ __launch_bounds__(B_THREADS, 8)
void attn_kernel(const float* __restrict__ x,
                 const float* __restrict__ Wa,
                 const float* __restrict__ ba,
                 float* __restrict__ out) {
    __shared__ float qs[B_WARPS][SEQ * QK_ST];
    __shared__ float eat[B_WARPS][SEQ * EAT_ST];
    __shared__ float was[UNITS];

    const int tid  = threadIdx.x;
    const int lane = tid & 31;
    const int w    = tid >> 5;
    const int batch = blockIdx.x * B_WARPS + w;

    if (tid < UNITS) was[tid] = Wa[tid];
    const float bav = __ldg(ba);
    __syncthreads();

    const float* qg = g_qk + (size_t)batch * SEQ * NQK;
    for (int p = lane; p < SEQ * NQK / 4; p += 32) {
        float4 v = *(const float4*)(qg + p * 4);
        int row = p >> 4;
        int c4  = p & 15;
        *(float4*)&qs[w][row * QK_ST + c4 * 4] = v;
    }
    __syncwarp();

    float sWa = 0.f;
    #pragma unroll
    for (int u = 0; u < UNITS; u++) sWa += was[u];

    for (int p = lane; p < SEQ * SEQ; p += 32) {
        int i = p / SEQ;
        int j = p - i * SEQ;
        const float4* qi = (const float4*)&qs[w][i * QK_ST];
        const float4* kj = (const float4*)&qs[w][j * QK_ST + UNITS];
        const float4* wa4 = (const float4*)was;
        float s = 0.f;
        #pragma unroll
        for (int u4 = 0; u4 < UNITS / 4; u4++) {
            float4 q = qi[u4];
            float4 k = kj[u4];
            float4 wa = wa4[u4];
            s = fmaf(wa.x, rcp_fast(__expf(2.f * (q.x + k.x)) + 1.f), s);
            s = fmaf(wa.y, rcp_fast(__expf(2.f * (q.y + k.y)) + 1.f), s);
            s = fmaf(wa.z, rcp_fast(__expf(2.f * (q.z + k.z)) + 1.f), s);
            s = fmaf(wa.w, rcp_fast(__expf(2.f * (q.w + k.w)) + 1.f), s);
        }
        float mask = (i == j) ? -10000.f : -fabsf((float)(i - j));
        eat[w][j * EAT_ST + i] = sWa - 2.f * s + bav + mask;
    }
    __syncwarp();

    if (lane < SEQ) {
        const int i = lane;
        float m = -1e30f;
        #pragma unroll
        for (int j = 0; j < SEQ; j++) m = fmaxf(m, eat[w][j * EAT_ST + i]);
        float ex[SEQ];
        float sum = 0.f;
        #pragma unroll
        for (int j = 0; j < SEQ; j++) {
            ex[j] = __expf(eat[w][j * EAT_ST + i] - m);
            sum += ex[j];
        }
        float inv = 1.f / sum;
        #pragma unroll
        for (int j = 0; j < SEQ; j++) eat[w][j * EAT_ST + i] = ex[j] * inv;
    }
    __syncwarp();

    const float* xb = x   + (size_t)batch * SEQ * DIM;
    float*       ob = out + (size_t)batch * SEQ * DIM;

    #pragma unroll 1
    for (int dc = 0; dc < DIM; dc += 64) {
        const int col = dc + lane * 2;
        float2 av[SEQ];
        #pragma unroll
        for (int i = 0; i < SEQ; i++) av[i] = make_float2(0.f, 0.f);

        #pragma unroll
        for (int j = 0; j < SEQ; j++) {
            float2 xj = __ldcs((const float2*)(xb + j * DIM + col));
            const float4* arow = (const float4*)&eat[w][j * EAT_ST];
            float4 A0 = arow[0];
            float4 A1 = arow[1];
            float4 A2 = arow[2];
            float4 A3 = arow[3];
            av[0].x  = fmaf(A0.x, xj.x, av[0].x);  av[0].y  = fmaf(A0.x, xj.y, av[0].y);
            av[1].x  = fmaf(A0.y, xj.x, av[1].x);  av[1].y  = fmaf(A0.y, xj.y, av[1].y);
            av[2].x  = fmaf(A0.z, xj.x, av[2].x);  av[2].y  = fmaf(A0.z, xj.y, av[2].y);
            av[3].x  = fmaf(A0.w, xj.x, av[3].x);  av[3].y  = fmaf(A0.w, xj.y, av[3].y);
            av[4].x  = fmaf(A1.x, xj.x, av[4].x);  av[4].y  = fmaf(A1.x, xj.y, av[4].y);
            av[5].x  = fmaf(A1.y, xj.x, av[5].x);  av[5].y  = fmaf(A1.y, xj.y, av[5].y);
            av[6].x  = fmaf(A1.z, xj.x, av[6].x);  av[6].y  = fmaf(A1.z, xj.y, av[6].y);
            av[7].x  = fmaf(A1.w, xj.x, av[7].x);  av[7].y  = fmaf(A1.w, xj.y, av[7].y);
            av[8].x  = fmaf(A2.x, xj.x, av[8].x);  av[8].y  = fmaf(A2.x, xj.y, av[8].y);
            av[9].x  = fmaf(A2.y, xj.x, av[9].x);  av[9].y  = fmaf(A2.y, xj.y, av[9].y);
            av[10].x = fmaf(A2.z, xj.x, av[10].x); av[10].y = fmaf(A2.z, xj.y, av[10].y);
            av[11].x = fmaf(A2.w, xj.x, av[11].x); av[11].y = fmaf(A2.w, xj.y, av[11].y);
            av[12].x = fmaf(A3.x, xj.x, av[12].x); av[12].y = fmaf(A3.x, xj.y, av[12].y);
            av[13].x = fmaf(A3.y, xj.x, av[13].x); av[13].y = fmaf(A3.y, xj.y, av[13].y);
            av[14].x = fmaf(A3.z, xj.x, av[14].x); av[14].y = fmaf(A3.z, xj.y, av[14].y);
        }
        #pragma unroll
        for (int i = 0; i < SEQ; i++)
            __stcs((float2*)(ob + i * DIM + col), av[i]);
    }
}

// ================= launch =================
extern "C" void kernel_launch(void* const* d_in, const int* in_sizes, int n_in,
                              void* d_out, int out_size) {
    const float* x  = (const float*)d_in[0];
    const float* Wt = (const float*)d_in[1];
    const float* Wx = (const float*)d_in[2];
    const float* bh = (const float*)d_in[3];
    const float* Wa = (const float*)d_in[4];
    const float* ba = (const float*)d_in[5];
    float* out = (float*)d_out;

    cudaFuncSetAttribute(gemm_qk_kernel,
                         cudaFuncAttributeMaxDynamicSharedMemorySize, A_SMEM_BYTES);

    prep_wf_kernel<<<64, 256>>>(Wt, Wx);
    gemm_qk_kernel<<<A_GRID, A_THREADS, A_SMEM_BYTES>>>(x, bh);
    attn_kernel<<<B_GRID, B_THREADS>>>(x, Wa, ba, out);
}

// round 15
// speedup vs baseline: 1.0533x; 1.0533x over previous
#include <cuda_runtime.h>
#include <cstdint>
#include <cstddef>

// ---------------- problem constants ----------------
#define BATCH   16384
#define SEQ     15
#define DIM     512
#define UNITS   32
#define NQK     64
#define TOTROWS (BATCH * SEQ)          // 245760

// ---------------- kernel A (GEMM) tiling ----------------
#define A_ROWS    256                  // 2 m16 tiles per warp x 8 warps
#define A_THREADS 256
#define A_GRID    (TOTROWS / A_ROWS)   // 960
#define KCHUNK    32
#define NCHUNKS   (DIM / KCHUNK)       // 16
#define GSTAGE    3
#define XS_STRIDE 36                   // x tile: [row][k], padded
#define XS_FLOATS (A_ROWS * XS_STRIDE) // 9216 floats = 36864 B per stage
#define A_SMEM_FLOATS (GSTAGE * XS_FLOATS)   // 27648
#define A_SMEM_BYTES  (A_SMEM_FLOATS * 4)    // 110592 -> 2 CTAs/SM

// ---------------- kernel B (attention) ----------------
#define B_WARPS   4
#define B_THREADS 128
#define B_GRID    (BATCH / B_WARPS)    // 4096
#define QK_ST     68
#define EAT_ST    16

// ---------------- scratch ----------------
__device__ float  g_qk[(size_t)TOTROWS * NQK];            // 62.9 MB
__device__ float2 g_Wf[NCHUNKS * 4 * 8 * 32];             // fragment-ordered W, 128 KB

// ---------------- helpers ----------------
__device__ __forceinline__ void cp16(void* dst, const void* src) {
    uint32_t d = (uint32_t)__cvta_generic_to_shared(dst);
    asm volatile("cp.async.cg.shared.global [%0], [%1], 16;" :: "r"(d), "l"(src));
}
#define CP_COMMIT() asm volatile("cp.async.commit_group;")
#define CP_WAIT1()  asm volatile("cp.async.wait_group 1;")
#define CP_WAIT0()  asm volatile("cp.async.wait_group 0;")

__device__ __forceinline__ void mma_tf32(float* c,
                                         uint32_t a0, uint32_t a1, uint32_t a2, uint32_t a3,
                                         uint32_t b0, uint32_t b1) {
    asm volatile(
        "mma.sync.aligned.m16n8k8.row.col.f32.tf32.tf32.f32 "
        "{%0,%1,%2,%3}, {%4,%5,%6,%7}, {%8,%9}, {%0,%1,%2,%3};"
        : "+f"(c[0]), "+f"(c[1]), "+f"(c[2]), "+f"(c[3])
        : "r"(a0), "r"(a1), "r"(a2), "r"(a3), "r"(b0), "r"(b1));
}

__device__ __forceinline__ float rcp_fast(float v) {
    float r;
    asm("rcp.approx.f32 %0, %1;" : "=f"(r) : "f"(v));
    return r;
}

// ================= kernel 0: W -> fragment-ordered layout =================
// g_Wf[((c*4 + k8)*8 + nt)*32 + lane] = { W[k][n], W[k+4][n] },
// n = nt*8 + (lane>>2), k = c*32 + k8*8 + (lane&3)  (validated R13).
__global__ void prep_wf_kernel(const float* __restrict__ Wt,
                               const float* __restrict__ Wx) {
    int idx  = blockIdx.x * 256 + threadIdx.x;   // 0..16383
    int lane = idx & 31;
    int nt   = (idx >> 5) & 7;
    int k8   = (idx >> 8) & 3;
    int c    = idx >> 10;
    int n    = nt * 8 + (lane >> 2);
    int k    = c * KCHUNK + k8 * 8 + (lane & 3);
    float v0 = (n < UNITS) ? Wt[k * UNITS + n]       : Wx[k * UNITS + (n - UNITS)];
    float v1 = (n < UNITS) ? Wt[(k + 4) * UNITS + n] : Wx[(k + 4) * UNITS + (n - UNITS)];
    g_Wf[idx] = make_float2(v0, v1);
}

// ================= kernel A: qk = x @ [Wt|Wx] + bh =================
// 256-row CTA tiles: each warp owns TWO m16 tiles sharing one set of
// B fragments per k8 -> B L2 traffic halved vs R13 (the measured limiter).
__global__ __launch_bounds__(A_THREADS, 2)
void gemm_qk_kernel(const float* __restrict__ x,
                    const float* __restrict__ bh) {
    extern __shared__ float sm[];

    const int tid  = threadIdx.x;
    const int lane = tid & 31;
    const int w    = tid >> 5;
    const long long rowbase = (long long)blockIdx.x * A_ROWS;

    auto issue = [&](int q) {
        float* xs = sm + (q % GSTAGE) * XS_FLOATS;
        const int kc = q * KCHUNK;
        #pragma unroll
        for (int r = 0; r < 8; r++) {
            int f   = tid + A_THREADS * r;   // 0..2047 float4 slots
            int row = f >> 3;                // 0..255
            int c4  = f & 7;                 // 0..7
            cp16(xs + row * XS_STRIDE + c4 * 4,
                 x + (rowbase + row) * DIM + kc + c4 * 4);
        }
        CP_COMMIT();
    };

    issue(0);
    issue(1);

    // acc[tile][nt][4] : two m16 tiles per warp
    float acc[2][8][4];
    #pragma unroll
    for (int t = 0; t < 2; t++)
        #pragma unroll
        for (int n = 0; n < 8; n++)
            #pragma unroll
            for (int q = 0; q < 4; q++) acc[t][n][q] = 0.f;

    const int g  = lane >> 2;
    const int tg = lane & 3;
    const int wr = w * 32;               // warp's 32-row block

    for (int c = 0; c < NCHUNKS; c++) {
        if (c == NCHUNKS - 1) { CP_WAIT0(); } else { CP_WAIT1(); }
        __syncthreads();   // chunk c visible; all warps done reading stage (c-1)%3

        if (c + 2 < NCHUNKS) issue(c + 2);   // overwrites stage (c-1)%3 (safe)

        float* xs = sm + (c % GSTAGE) * XS_FLOATS;
        const float2* wf = g_Wf + (size_t)(c * 4) * 8 * 32 + lane;

        #pragma unroll
        for (int k8 = 0; k8 < 4; k8++) {
            const int kb = k8 * 8;
            // A fragments for both tiles (rows wr..wr+15, wr+16..wr+31)
            const float* ar0 = xs + (wr + g) * XS_STRIDE + kb + tg;
            const float* ar1 = ar0 + 16 * XS_STRIDE;
            uint32_t t0a0 = __float_as_uint(ar0[0]);
            uint32_t t0a1 = __float_as_uint(ar0[8 * XS_STRIDE]);
            uint32_t t0a2 = __float_as_uint(ar0[4]);
            uint32_t t0a3 = __float_as_uint(ar0[8 * XS_STRIDE + 4]);
            uint32_t t1a0 = __float_as_uint(ar1[0]);
            uint32_t t1a1 = __float_as_uint(ar1[8 * XS_STRIDE]);
            uint32_t t1a2 = __float_as_uint(ar1[4]);
            uint32_t t1a3 = __float_as_uint(ar1[8 * XS_STRIDE + 4]);
            // B fragments: loaded ONCE, feed both tiles (16 mma)
            const float2* wk = wf + (size_t)k8 * 8 * 32;
            float2 b[8];
            #pragma unroll
            for (int nt = 0; nt < 8; nt++) b[nt] = __ldg(wk + nt * 32);
            #pragma unroll
            for (int nt = 0; nt < 8; nt++) {
                uint32_t b0 = __float_as_uint(b[nt].x);
                uint32_t b1 = __float_as_uint(b[nt].y);
                mma_tf32(acc[0][nt], t0a0, t0a1, t0a2, t0a3, b0, b1);
                mma_tf32(acc[1][nt], t1a0, t1a1, t1a2, t1a3, b0, b1);
            }
        }
    }

    // epilogue: both tiles (+bh on cols < 32)
    #pragma unroll
    for (int t = 0; t < 2; t++) {
        const int r0 = wr + t * 16 + g;
        const int r1 = r0 + 8;
        #pragma unroll
        for (int nt = 0; nt < 8; nt++) {
            int cc = nt * 8 + tg * 2;
            float b0 = (cc     < UNITS) ? __ldg(bh + cc)     : 0.f;
            float b1 = (cc + 1 < UNITS) ? __ldg(bh + cc + 1) : 0.f;
            float2 v0 = make_float2(acc[t][nt][0] + b0, acc[t][nt][1] + b1);
            float2 v1 = make_float2(acc[t][nt][2] + b0, acc[t][nt][3] + b1);
            *(float2*)(g_qk + (size_t)(rowbase + r0) * NQK + cc) = v0;
            *(float2*)(g_qk + (size_t)(rowbase + r1) * NQK + cc) = v1;
        }
    }
}

// ================= kernel B: e/softmax/AV (round-6 control, 200us) =================
__global__ __launch_bounds__(B_THREADS, 8)
void attn_kernel(const float* __restrict__ x,
                 const float* __restrict__ Wa,
                 const float* __restrict__ ba,
                 float* __restrict__ out) {
    __shared__ float qs[B_WARPS][SEQ * QK_ST];
    __shared__ float eat[B_WARPS][SEQ * EAT_ST];
    __shared__ float was[UNITS];

    const int tid  = threadIdx.x;
    const int lane = tid & 31;
    const int w    = tid >> 5;
    const int batch = blockIdx.x * B_WARPS + w;

    if (tid < UNITS) was[tid] = Wa[tid];
    const float bav = __ldg(ba);
    __syncthreads();

    const float* qg = g_qk + (size_t)batch * SEQ * NQK;
    for (int p = lane; p < SEQ * NQK / 4; p += 32) {
        float4 v = *(const float4*)(qg + p * 4);
        int row = p >> 4;
        int c4  = p & 15;
        *(float4*)&qs[w][row * QK_ST + c4 * 4] = v;
    }
    __syncwarp();

    float sWa = 0.f;
    #pragma unroll
    for (int u = 0; u < UNITS; u++) sWa += was[u];

    for (int p = lane; p < SEQ * SEQ; p += 32) {
        int i = p / SEQ;
        int j = p - i * SEQ;
        const float4* qi = (const float4*)&qs[w][i * QK_ST];
        const float4* kj = (const float4*)&qs[w][j * QK_ST + UNITS];
        const float4* wa4 = (const float4*)was;
        float s = 0.f;
        #pragma unroll
        for (int u4 = 0; u4 < UNITS / 4; u4++) {
            float4 q = qi[u4];
            float4 k = kj[u4];
            float4 wa = wa4[u4];
            s = fmaf(wa.x, rcp_fast(__expf(2.f * (q.x + k.x)) + 1.f), s);
            s = fmaf(wa.y, rcp_fast(__expf(2.f * (q.y + k.y)) + 1.f), s);
            s = fmaf(wa.z, rcp_fast(__expf(2.f * (q.z + k.z)) + 1.f), s);
            s = fmaf(wa.w, rcp_fast(__expf(2.f * (q.w + k.w)) + 1.f), s);
        }
        float mask = (i == j) ? -10000.f : -fabsf((float)(i - j));
        eat[w][j * EAT_ST + i] = sWa - 2.f * s + bav + mask;
    }
    __syncwarp();

    if (lane < SEQ) {
        const int i = lane;
        float m = -1e30f;
        #pragma unroll
        for (int j = 0; j < SEQ; j++) m = fmaxf(m, eat[w][j * EAT_ST + i]);
        float ex[SEQ];
        float sum = 0.f;
        #pragma unroll
        for (int j = 0; j < SEQ; j++) {
            ex[j] = __expf(eat[w][j * EAT_ST + i] - m);
            sum += ex[j];
        }
        float inv = 1.f / sum;
        #pragma unroll
        for (int j = 0; j < SEQ; j++) eat[w][j * EAT_ST + i] = ex[j] * inv;
    }
    __syncwarp();

    const float* xb = x   + (size_t)batch * SEQ * DIM;
    float*       ob = out + (size_t)batch * SEQ * DIM;

    #pragma unroll 1
    for (int dc = 0; dc < DIM; dc += 64) {
        const int col = dc + lane * 2;
        float2 av[SEQ];
        #pragma unroll
        for (int i = 0; i < SEQ; i++) av[i] = make_float2(0.f, 0.f);

        #pragma unroll
        for (int j = 0; j < SEQ; j++) {
            float2 xj = __ldcs((const float2*)(xb + j * DIM + col));
            const float4* arow = (const float4*)&eat[w][j * EAT_ST];
            float4 A0 = arow[0];
            float4 A1 = arow[1];
            float4 A2 = arow[2];
            float4 A3 = arow[3];
            av[0].x  = fmaf(A0.x, xj.x, av[0].x);  av[0].y  = fmaf(A0.x, xj.y, av[0].y);
            av[1].x  = fmaf(A0.y, xj.x, av[1].x);  av[1].y  = fmaf(A0.y, xj.y, av[1].y);
            av[2].x  = fmaf(A0.z, xj.x, av[2].x);  av[2].y  = fmaf(A0.z, xj.y, av[2].y);
            av[3].x  = fmaf(A0.w, xj.x, av[3].x);  av[3].y  = fmaf(A0.w, xj.y, av[3].y);
            av[4].x  = fmaf(A1.x, xj.x, av[4].x);  av[4].y  = fmaf(A1.x, xj.y, av[4].y);
            av[5].x  = fmaf(A1.y, xj.x, av[5].x);  av[5].y  = fmaf(A1.y, xj.y, av[5].y);
            av[6].x  = fmaf(A1.z, xj.x, av[6].x);  av[6].y  = fmaf(A1.z, xj.y, av[6].y);
            av[7].x  = fmaf(A1.w, xj.x, av[7].x);  av[7].y  = fmaf(A1.w, xj.y, av[7].y);
            av[8].x  = fmaf(A2.x, xj.x, av[8].x);  av[8].y  = fmaf(A2.x, xj.y, av[8].y);
            av[9].x  = fmaf(A2.y, xj.x, av[9].x);  av[9].y  = fmaf(A2.y, xj.y, av[9].y);
            av[10].x = fmaf(A2.z, xj.x, av[10].x); av[10].y = fmaf(A2.z, xj.y, av[10].y);
            av[11].x = fmaf(A2.w, xj.x, av[11].x); av[11].y = fmaf(A2.w, xj.y, av[11].y);
            av[12].x = fmaf(A3.x, xj.x, av[12].x); av[12].y = fmaf(A3.x, xj.y, av[12].y);
            av[13].x = fmaf(A3.y, xj.x, av[13].x); av[13].y = fmaf(A3.y, xj.y, av[13].y);
            av[14].x = fmaf(A3.z, xj.x, av[14].x); av[14].y = fmaf(A3.z, xj.y, av[14].y);
        }
        #pragma unroll
        for (int i = 0; i < SEQ; i++)
            __stcs((float2*)(ob + i * DIM + col), av[i]);
    }
}

// ================= launch =================
extern "C" void kernel_launch(void* const* d_in, const int* in_sizes, int n_in,
                              void* d_out, int out_size) {
    const float* x  = (const float*)d_in[0];
    const float* Wt = (const float*)d_in[1];
    const float* Wx = (const float*)d_in[2];
    const float* bh = (const float*)d_in[3];
    const float* Wa = (const float*)d_in[4];
    const float* ba = (const float*)d_in[5];
    float* out = (float*)d_out;

    cudaFuncSetAttribute(gemm_qk_kernel,
                         cudaFuncAttributeMaxDynamicSharedMemorySize, A_SMEM_BYTES);

    prep_wf_kernel<<<64, 256>>>(Wt, Wx);
    gemm_qk_kernel<<<A_GRID, A_THREADS, A_SMEM_BYTES>>>(x, bh);
    attn_kernel<<<B_GRID, B_THREADS>>>(x, Wa, ba, out);
}

// round 16
// speedup vs baseline: 1.0570x; 1.0035x over previous
#include <cuda_runtime.h>
#include <cstdint>
#include <cstddef>

// ---------------- problem constants ----------------
#define BATCH   16384
#define SEQ     15
#define DIM     512
#define UNITS   32
#define NQK     64
#define TOTROWS (BATCH * SEQ)          // 245760

// ---------------- pipeline ----------------
#define PIPE      4
#define BATCH_PC  (BATCH / PIPE)       // 4096
#define ROWS_PC   (BATCH_PC * SEQ)     // 61440

// ---------------- kernel A (GEMM) tiling — R6 config (best measured) ----------------
#define A_ROWS    128
#define A_THREADS 256
#define A_GRID_PC (ROWS_PC / A_ROWS)   // 480
#define KCHUNK    32
#define NCHUNKS   (DIM / KCHUNK)       // 16
#define NSTAGE    3
#define XS_STRIDE 36
#define WS_STRIDE 68
#define XS_FLOATS (A_ROWS * XS_STRIDE) // 4608
#define WS_FLOATS (KCHUNK * WS_STRIDE) // 2176
#define STAGE_FLOATS (XS_FLOATS + WS_FLOATS)            // 6784
#define A_SMEM_FLOATS (NSTAGE * STAGE_FLOATS)           // 20352
#define A_SMEM_BYTES  (A_SMEM_FLOATS * 4)               // 81408

// ---------------- kernel B (attention) — R6 config ----------------
#define B_WARPS   4
#define B_THREADS 128
#define B_GRID_PC (BATCH_PC / B_WARPS) // 1024
#define QK_ST     68
#define EAT_ST    16

// ---------------- scratch ----------------
__device__ float g_qk[(size_t)TOTROWS * NQK];   // 62.9 MB

// ---------------- helpers ----------------
__device__ __forceinline__ void cp16(void* dst, const void* src) {
    uint32_t d = (uint32_t)__cvta_generic_to_shared(dst);
    asm volatile("cp.async.cg.shared.global [%0], [%1], 16;" :: "r"(d), "l"(src));
}
#define CP_COMMIT() asm volatile("cp.async.commit_group;")
#define CP_WAIT1()  asm volatile("cp.async.wait_group 1;")
#define CP_WAIT0()  asm volatile("cp.async.wait_group 0;")

__device__ __forceinline__ void mma_tf32(float* c,
                                         uint32_t a0, uint32_t a1, uint32_t a2, uint32_t a3,
                                         uint32_t b0, uint32_t b1) {
    asm volatile(
        "mma.sync.aligned.m16n8k8.row.col.f32.tf32.tf32.f32 "
        "{%0,%1,%2,%3}, {%4,%5,%6,%7}, {%8,%9}, {%0,%1,%2,%3};"
        : "+f"(c[0]), "+f"(c[1]), "+f"(c[2]), "+f"(c[3])
        : "r"(a0), "r"(a1), "r"(a2), "r"(a3), "r"(b0), "r"(b1));
}

__device__ __forceinline__ float rcp_fast(float v) {
    float r;
    asm("rcp.approx.f32 %0, %1;" : "=f"(r) : "f"(v));
    return r;
}

// ================= kernel A: qk = x @ [Wt|Wx] + bh (R6, chunked) =================
__global__ __launch_bounds__(A_THREADS, 2)
void gemm_qk_kernel(const float* __restrict__ x,
                    const float* __restrict__ Wt,
                    const float* __restrict__ Wx,
                    const float* __restrict__ bh,
                    int rowoff) {
    extern __shared__ float sm[];

    const int tid  = threadIdx.x;
    const int lane = tid & 31;
    const int w    = tid >> 5;
    const long long rowbase = (long long)rowoff + (long long)blockIdx.x * A_ROWS;

    auto issue = [&](int stage, int kc) {
        float* xs = sm + stage * STAGE_FLOATS;
        float* ws = xs + XS_FLOATS;
        #pragma unroll
        for (int r = 0; r < 4; r++) {
            int f   = tid + A_THREADS * r;
            int row = f >> 3;
            int c4  = f & 7;
            cp16(xs + row * XS_STRIDE + c4 * 4,
                 x + (rowbase + row) * DIM + kc + c4 * 4);
        }
        #pragma unroll
        for (int r = 0; r < 2; r++) {
            int e  = tid + A_THREADS * r;
            int k  = e >> 4;
            int n4 = e & 15;
            const float* src = (n4 < 8)
                ? Wt + (size_t)(kc + k) * UNITS + n4 * 4
                : Wx + (size_t)(kc + k) * UNITS + (n4 - 8) * 4;
            cp16(ws + k * WS_STRIDE + n4 * 4, src);
        }
        CP_COMMIT();
    };

    issue(0, 0);
    issue(1, KCHUNK);

    float acc[8][4];
    #pragma unroll
    for (int n = 0; n < 8; n++)
        #pragma unroll
        for (int q = 0; q < 4; q++) acc[n][q] = 0.f;

    const int g  = lane >> 2;
    const int tg = lane & 3;

    int stage = 0;
    for (int c = 0; c < NCHUNKS; c++) {
        if (c == NCHUNKS - 1) { CP_WAIT0(); } else { CP_WAIT1(); }
        __syncthreads();

        if (c + 2 < NCHUNKS) {
            int ns = stage + 2; if (ns >= NSTAGE) ns -= NSTAGE;
            issue(ns, (c + 2) * KCHUNK);
        }

        float* xs = sm + stage * STAGE_FLOATS;
        float* ws = xs + XS_FLOATS;

        #pragma unroll
        for (int k8 = 0; k8 < 4; k8++) {
            const int kb = k8 * 8;
            const float* ar = xs + (w * 16 + g) * XS_STRIDE + kb + tg;
            uint32_t a0 = __float_as_uint(ar[0]);
            uint32_t a1 = __float_as_uint(ar[8 * XS_STRIDE]);
            uint32_t a2 = __float_as_uint(ar[4]);
            uint32_t a3 = __float_as_uint(ar[8 * XS_STRIDE + 4]);
            const float* br = ws + (kb + tg) * WS_STRIDE + g;
            #pragma unroll
            for (int nt = 0; nt < 8; nt++) {
                mma_tf32(acc[nt], a0, a1, a2, a3,
                         __float_as_uint(br[nt * 8]),
                         __float_as_uint(br[4 * WS_STRIDE + nt * 8]));
            }
        }
        if (++stage >= NSTAGE) stage -= NSTAGE;
    }

    const int r0 = w * 16 + g;
    const int r1 = r0 + 8;
    #pragma unroll
    for (int nt = 0; nt < 8; nt++) {
        int cc = nt * 8 + tg * 2;
        float b0 = (cc     < UNITS) ? __ldg(bh + cc)     : 0.f;
        float b1 = (cc + 1 < UNITS) ? __ldg(bh + cc + 1) : 0.f;
        float2 v0 = make_float2(acc[nt][0] + b0, acc[nt][1] + b1);
        float2 v1 = make_float2(acc[nt][2] + b0, acc[nt][3] + b1);
        *(float2*)(g_qk + (size_t)(rowbase + r0) * NQK + cc) = v0;
        *(float2*)(g_qk + (size_t)(rowbase + r1) * NQK + cc) = v1;
    }
}

// ================= kernel B: e/softmax/AV (R6, chunked) =================
__global__ __launch_bounds__(B_THREADS, 8)
void attn_kernel(const float* __restrict__ x,
                 const float* __restrict__ Wa,
                 const float* __restrict__ ba,
                 float* __restrict__ out,
                 int batchoff) {
    __shared__ float qs[B_WARPS][SEQ * QK_ST];
    __shared__ float eat[B_WARPS][SEQ * EAT_ST];
    __shared__ float was[UNITS];

    const int tid  = threadIdx.x;
    const int lane = tid & 31;
    const int w    = tid >> 5;
    const int batch = batchoff + blockIdx.x * B_WARPS + w;

    if (tid < UNITS) was[tid] = Wa[tid];
    const float bav = __ldg(ba);
    __syncthreads();

    const float* qg = g_qk + (size_t)batch * SEQ * NQK;
    for (int p = lane; p < SEQ * NQK / 4; p += 32) {
        float4 v = *(const float4*)(qg + p * 4);
        int row = p >> 4;
        int c4  = p & 15;
        *(float4*)&qs[w][row * QK_ST + c4 * 4] = v;
    }
    __syncwarp();

    float sWa = 0.f;
    #pragma unroll
    for (int u = 0; u < UNITS; u++) sWa += was[u];

    for (int p = lane; p < SEQ * SEQ; p += 32) {
        int i = p / SEQ;
        int j = p - i * SEQ;
        const float4* qi = (const float4*)&qs[w][i * QK_ST];
        const float4* kj = (const float4*)&qs[w][j * QK_ST + UNITS];
        const float4* wa4 = (const float4*)was;
        float s = 0.f;
        #pragma unroll
        for (int u4 = 0; u4 < UNITS / 4; u4++) {
            float4 q = qi[u4];
            float4 k = kj[u4];
            float4 wa = wa4[u4];
            s = fmaf(wa.x, rcp_fast(__expf(2.f * (q.x + k.x)) + 1.f), s);
            s = fmaf(wa.y, rcp_fast(__expf(2.f * (q.y + k.y)) + 1.f), s);
            s = fmaf(wa.z, rcp_fast(__expf(2.f * (q.z + k.z)) + 1.f), s);
            s = fmaf(wa.w, rcp_fast(__expf(2.f * (q.w + k.w)) + 1.f), s);
        }
        float mask = (i == j) ? -10000.f : -fabsf((float)(i - j));
        eat[w][j * EAT_ST + i] = sWa - 2.f * s + bav + mask;
    }
    __syncwarp();

    if (lane < SEQ) {
        const int i = lane;
        float m = -1e30f;
        #pragma unroll
        for (int j = 0; j < SEQ; j++) m = fmaxf(m, eat[w][j * EAT_ST + i]);
        float ex[SEQ];
        float sum = 0.f;
        #pragma unroll
        for (int j = 0; j < SEQ; j++) {
            ex[j] = __expf(eat[w][j * EAT_ST + i] - m);
            sum += ex[j];
        }
        float inv = 1.f / sum;
        #pragma unroll
        for (int j = 0; j < SEQ; j++) eat[w][j * EAT_ST + i] = ex[j] * inv;
    }
    __syncwarp();

    const float* xb = x   + (size_t)batch * SEQ * DIM;
    float*       ob = out + (size_t)batch * SEQ * DIM;

    #pragma unroll 1
    for (int dc = 0; dc < DIM; dc += 64) {
        const int col = dc + lane * 2;
        float2 av[SEQ];
        #pragma unroll
        for (int i = 0; i < SEQ; i++) av[i] = make_float2(0.f, 0.f);

        #pragma unroll
        for (int j = 0; j < SEQ; j++) {
            float2 xj = __ldcs((const float2*)(xb + j * DIM + col));
            const float4* arow = (const float4*)&eat[w][j * EAT_ST];
            float4 A0 = arow[0];
            float4 A1 = arow[1];
            float4 A2 = arow[2];
            float4 A3 = arow[3];
            av[0].x  = fmaf(A0.x, xj.x, av[0].x);  av[0].y  = fmaf(A0.x, xj.y, av[0].y);
            av[1].x  = fmaf(A0.y, xj.x, av[1].x);  av[1].y  = fmaf(A0.y, xj.y, av[1].y);
            av[2].x  = fmaf(A0.z, xj.x, av[2].x);  av[2].y  = fmaf(A0.z, xj.y, av[2].y);
            av[3].x  = fmaf(A0.w, xj.x, av[3].x);  av[3].y  = fmaf(A0.w, xj.y, av[3].y);
            av[4].x  = fmaf(A1.x, xj.x, av[4].x);  av[4].y  = fmaf(A1.x, xj.y, av[4].y);
            av[5].x  = fmaf(A1.y, xj.x, av[5].x);  av[5].y  = fmaf(A1.y, xj.y, av[5].y);
            av[6].x  = fmaf(A1.z, xj.x, av[6].x);  av[6].y  = fmaf(A1.z, xj.y, av[6].y);
            av[7].x  = fmaf(A1.w, xj.x, av[7].x);  av[7].y  = fmaf(A1.w, xj.y, av[7].y);
            av[8].x  = fmaf(A2.x, xj.x, av[8].x);  av[8].y  = fmaf(A2.x, xj.y, av[8].y);
            av[9].x  = fmaf(A2.y, xj.x, av[9].x);  av[9].y  = fmaf(A2.y, xj.y, av[9].y);
            av[10].x = fmaf(A2.z, xj.x, av[10].x); av[10].y = fmaf(A2.z, xj.y, av[10].y);
            av[11].x = fmaf(A2.w, xj.x, av[11].x); av[11].y = fmaf(A2.w, xj.y, av[11].y);
            av[12].x = fmaf(A3.x, xj.x, av[12].x); av[12].y = fmaf(A3.x, xj.y, av[12].y);
            av[13].x = fmaf(A3.y, xj.x, av[13].x); av[13].y = fmaf(A3.y, xj.y, av[13].y);
            av[14].x = fmaf(A3.z, xj.x, av[14].x); av[14].y = fmaf(A3.z, xj.y, av[14].y);
        }
        #pragma unroll
        for (int i = 0; i < SEQ; i++)
            __stcs((float2*)(ob + i * DIM + col), av[i]);
    }
}

// ================= launch: TWO explicit non-blocking streams =================
// R9 bug: gemm ran on the LEGACY stream, which implicitly synchronizes with
// every other stream -> forced serialization. Both pipelines now live on
// explicit non-blocking streams; the capture-origin stream only forks/joins.
namespace {
struct PipeRes {
    cudaStream_t s1, s2;               // s1: gemm, s2: attn
    cudaEvent_t  fork;
    cudaEvent_t  gdone[PIPE];
    cudaEvent_t  join;
    PipeRes() {
        cudaStreamCreateWithFlags(&s1, cudaStreamNonBlocking);
        cudaStreamCreateWithFlags(&s2, cudaStreamNonBlocking);
        cudaEventCreateWithFlags(&fork, cudaEventDisableTiming);
        for (int i = 0; i < PIPE; i++)
            cudaEventCreateWithFlags(&gdone[i], cudaEventDisableTiming);
        cudaEventCreateWithFlags(&join, cudaEventDisableTiming);
    }
};
}

extern "C" void kernel_launch(void* const* d_in, const int* in_sizes, int n_in,
                              void* d_out, int out_size) {
    const float* x  = (const float*)d_in[0];
    const float* Wt = (const float*)d_in[1];
    const float* Wx = (const float*)d_in[2];
    const float* bh = (const float*)d_in[3];
    const float* Wa = (const float*)d_in[4];
    const float* ba = (const float*)d_in[5];
    float* out = (float*)d_out;

    static PipeRes pr;

    cudaFuncSetAttribute(gemm_qk_kernel,
                         cudaFuncAttributeMaxDynamicSharedMemorySize, A_SMEM_BYTES);

    // fork from capture-origin stream
    cudaEventRecord(pr.fork, 0);
    cudaStreamWaitEvent(pr.s1, pr.fork, 0);
    cudaStreamWaitEvent(pr.s2, pr.fork, 0);

    for (int c = 0; c < PIPE; c++) {
        gemm_qk_kernel<<<A_GRID_PC, A_THREADS, A_SMEM_BYTES, pr.s1>>>(
            x, Wt, Wx, bh, c * ROWS_PC);
        cudaEventRecord(pr.gdone[c], pr.s1);
        cudaStreamWaitEvent(pr.s2, pr.gdone[c], 0);
        attn_kernel<<<B_GRID_PC, B_THREADS, 0, pr.s2>>>(
            x, Wa, ba, out, c * BATCH_PC);
    }

    // join: all attn work (which transitively depends on all gemm work)
    cudaEventRecord(pr.join, pr.s2);
    cudaStreamWaitEvent(0, pr.join, 0);
}

// round 17
// speedup vs baseline: 1.2118x; 1.1465x over previous
#include <cuda_runtime.h>
#include <cstdint>
#include <cstddef>

// ---------------- problem constants ----------------
#define BATCH   16384
#define SEQ     15
#define DIM     512
#define UNITS   32
#define NQK     64
#define TOTROWS (BATCH * SEQ)          // 245760

// ---------------- kernel A (GEMM) tiling ----------------
#define A_ROWS    128
#define A_THREADS 256
#define A_GRID    (TOTROWS / A_ROWS)   // 1920
#define KCHUNK    32
#define NCHUNKS   (DIM / KCHUNK)       // 16
#define NSTAGE    2
#define XS_STRIDE 36
#define WS_STRIDE 68
#define XS_FLOATS (A_ROWS * XS_STRIDE) // 4608
#define WS_FLOATS (KCHUNK * WS_STRIDE) // 2176
#define STAGE_FLOATS (XS_FLOATS + WS_FLOATS)            // 6784
#define A_SMEM_FLOATS (NSTAGE * STAGE_FLOATS)           // 13568
#define A_SMEM_BYTES  (A_SMEM_FLOATS * 4)               // 54272 -> 4 CTAs/SM

// ---------------- kernel B (attention) ----------------
#define B_WARPS   4
#define B_THREADS 128
#define B_GRID    (BATCH / B_WARPS)    // 4096
#define QK_ST     68
#define EAT_ST    16

// ---------------- scratch ----------------
__device__ float g_qk[(size_t)TOTROWS * NQK];   // 62.9 MB

// ---------------- helpers ----------------
__device__ __forceinline__ void cp16(void* dst, const void* src) {
    uint32_t d = (uint32_t)__cvta_generic_to_shared(dst);
    asm volatile("cp.async.cg.shared.global [%0], [%1], 16;" :: "r"(d), "l"(src));
}
#define CP_COMMIT() asm volatile("cp.async.commit_group;")
#define CP_WAIT1()  asm volatile("cp.async.wait_group 1;")
#define CP_WAIT0()  asm volatile("cp.async.wait_group 0;")

__device__ __forceinline__ void mma_tf32(float* c,
                                         uint32_t a0, uint32_t a1, uint32_t a2, uint32_t a3,
                                         uint32_t b0, uint32_t b1) {
    asm volatile(
        "mma.sync.aligned.m16n8k8.row.col.f32.tf32.tf32.f32 "
        "{%0,%1,%2,%3}, {%4,%5,%6,%7}, {%8,%9}, {%0,%1,%2,%3};"
        : "+f"(c[0]), "+f"(c[1]), "+f"(c[2]), "+f"(c[3])
        : "r"(a0), "r"(a1), "r"(a2), "r"(a3), "r"(b0), "r"(b1));
}

__device__ __forceinline__ float rcp_fast(float v) {
    float r;
    asm("rcp.approx.f32 %0, %1;" : "=f"(r) : "f"(v));
    return r;
}

// ================= kernel A: qk = x @ [Wt|Wx] + bh =================
// R6 math, 2-stage ring, 4 CTAs/SM (occupancy test with tile size HELD).
__global__ __launch_bounds__(A_THREADS, 4)
void gemm_qk_kernel(const float* __restrict__ x,
                    const float* __restrict__ Wt,
                    const float* __restrict__ Wx,
                    const float* __restrict__ bh) {
    extern __shared__ float sm[];

    const int tid  = threadIdx.x;
    const int lane = tid & 31;
    const int w    = tid >> 5;
    const long long rowbase = (long long)blockIdx.x * A_ROWS;

    auto issue = [&](int q) {
        float* xs = sm + (q & 1) * STAGE_FLOATS;
        float* ws = xs + XS_FLOATS;
        const int kc = q * KCHUNK;
        #pragma unroll
        for (int r = 0; r < 4; r++) {
            int f   = tid + A_THREADS * r;
            int row = f >> 3;
            int c4  = f & 7;
            cp16(xs + row * XS_STRIDE + c4 * 4,
                 x + (rowbase + row) * DIM + kc + c4 * 4);
        }
        #pragma unroll
        for (int r = 0; r < 2; r++) {
            int e  = tid + A_THREADS * r;
            int k  = e >> 4;
            int n4 = e & 15;
            const float* src = (n4 < 8)
                ? Wt + (size_t)(kc + k) * UNITS + n4 * 4
                : Wx + (size_t)(kc + k) * UNITS + (n4 - 8) * 4;
            cp16(ws + k * WS_STRIDE + n4 * 4, src);
        }
        CP_COMMIT();
    };

    issue(0);

    float acc[8][4];
    #pragma unroll
    for (int n = 0; n < 8; n++)
        #pragma unroll
        for (int q = 0; q < 4; q++) acc[n][q] = 0.f;

    const int g  = lane >> 2;
    const int tg = lane & 3;

    for (int c = 0; c < NCHUNKS; c++) {
        // prefetch next chunk into the other stage; its previous occupant
        // (chunk c-1) was fully read before last iteration's trailing sync
        if (c + 1 < NCHUNKS) { issue(c + 1); CP_WAIT1(); }
        else                 { CP_WAIT0(); }
        __syncthreads();   // chunk c visible to all warps

        float* xs = sm + (c & 1) * STAGE_FLOATS;
        float* ws = xs + XS_FLOATS;

        #pragma unroll
        for (int k8 = 0; k8 < 4; k8++) {
            const int kb = k8 * 8;
            const float* ar = xs + (w * 16 + g) * XS_STRIDE + kb + tg;
            uint32_t a0 = __float_as_uint(ar[0]);
            uint32_t a1 = __float_as_uint(ar[8 * XS_STRIDE]);
            uint32_t a2 = __float_as_uint(ar[4]);
            uint32_t a3 = __float_as_uint(ar[8 * XS_STRIDE + 4]);
            const float* br = ws + (kb + tg) * WS_STRIDE + g;
            #pragma unroll
            for (int nt = 0; nt < 8; nt++) {
                mma_tf32(acc[nt], a0, a1, a2, a3,
                         __float_as_uint(br[nt * 8]),
                         __float_as_uint(br[4 * WS_STRIDE + nt * 8]));
            }
        }
        __syncthreads();   // all warps done reading stage c&1 before it's refilled
    }

    const int r0 = w * 16 + g;
    const int r1 = r0 + 8;
    #pragma unroll
    for (int nt = 0; nt < 8; nt++) {
        int cc = nt * 8 + tg * 2;
        float b0 = (cc     < UNITS) ? __ldg(bh + cc)     : 0.f;
        float b1 = (cc + 1 < UNITS) ? __ldg(bh + cc + 1) : 0.f;
        float2 v0 = make_float2(acc[nt][0] + b0, acc[nt][1] + b1);
        float2 v1 = make_float2(acc[nt][2] + b0, acc[nt][3] + b1);
        *(float2*)(g_qk + (size_t)(rowbase + r0) * NQK + cc) = v0;
        *(float2*)(g_qk + (size_t)(rowbase + r1) * NQK + cc) = v1;
    }
}

// ================= kernel B: e/softmax/AV (round-6 control, 200us) =================
__global__ __launch_bounds__(B_THREADS, 8)
void attn_kernel(const float* __restrict__ x,
                 const float* __restrict__ Wa,
                 const float* __restrict__ ba,
                 float* __restrict__ out) {
    __shared__ float qs[B_WARPS][SEQ * QK_ST];
    __shared__ float eat[B_WARPS][SEQ * EAT_ST];
    __shared__ float was[UNITS];

    const int tid  = threadIdx.x;
    const int lane = tid & 31;
    const int w    = tid >> 5;
    const int batch = blockIdx.x * B_WARPS + w;

    if (tid < UNITS) was[tid] = Wa[tid];
    const float bav = __ldg(ba);
    __syncthreads();

    const float* qg = g_qk + (size_t)batch * SEQ * NQK;
    for (int p = lane; p < SEQ * NQK / 4; p += 32) {
        float4 v = *(const float4*)(qg + p * 4);
        int row = p >> 4;
        int c4  = p & 15;
        *(float4*)&qs[w][row * QK_ST + c4 * 4] = v;
    }
    __syncwarp();

    float sWa = 0.f;
    #pragma unroll
    for (int u = 0; u < UNITS; u++) sWa += was[u];

    for (int p = lane; p < SEQ * SEQ; p += 32) {
        int i = p / SEQ;
        int j = p - i * SEQ;
        const float4* qi = (const float4*)&qs[w][i * QK_ST];
        const float4* kj = (const float4*)&qs[w][j * QK_ST + UNITS];
        const float4* wa4 = (const float4*)was;
        float s = 0.f;
        #pragma unroll
        for (int u4 = 0; u4 < UNITS / 4; u4++) {
            float4 q = qi[u4];
            float4 k = kj[u4];
            float4 wa = wa4[u4];
            s = fmaf(wa.x, rcp_fast(__expf(2.f * (q.x + k.x)) + 1.f), s);
            s = fmaf(wa.y, rcp_fast(__expf(2.f * (q.y + k.y)) + 1.f), s);
            s = fmaf(wa.z, rcp_fast(__expf(2.f * (q.z + k.z)) + 1.f), s);
            s = fmaf(wa.w, rcp_fast(__expf(2.f * (q.w + k.w)) + 1.f), s);
        }
        float mask = (i == j) ? -10000.f : -fabsf((float)(i - j));
        eat[w][j * EAT_ST + i] = sWa - 2.f * s + bav + mask;
    }
    __syncwarp();

    if (lane < SEQ) {
        const int i = lane;
        float m = -1e30f;
        #pragma unroll
        for (int j = 0; j < SEQ; j++) m = fmaxf(m, eat[w][j * EAT_ST + i]);
        float ex[SEQ];
        float sum = 0.f;
        #pragma unroll
        for (int j = 0; j < SEQ; j++) {
            ex[j] = __expf(eat[w][j * EAT_ST + i] - m);
            sum += ex[j];
        }
        float inv = 1.f / sum;
        #pragma unroll
        for (int j = 0; j < SEQ; j++) eat[w][j * EAT_ST + i] = ex[j] * inv;
    }
    __syncwarp();

    const float* xb = x   + (size_t)batch * SEQ * DIM;
    float*       ob = out + (size_t)batch * SEQ * DIM;

    #pragma unroll 1
    for (int dc = 0; dc < DIM; dc += 64) {
        const int col = dc + lane * 2;
        float2 av[SEQ];
        #pragma unroll
        for (int i = 0; i < SEQ; i++) av[i] = make_float2(0.f, 0.f);

        #pragma unroll
        for (int j = 0; j < SEQ; j++) {
            float2 xj = __ldcs((const float2*)(xb + j * DIM + col));
            const float4* arow = (const float4*)&eat[w][j * EAT_ST];
            float4 A0 = arow[0];
            float4 A1 = arow[1];
            float4 A2 = arow[2];
            float4 A3 = arow[3];
            av[0].x  = fmaf(A0.x, xj.x, av[0].x);  av[0].y  = fmaf(A0.x, xj.y, av[0].y);
            av[1].x  = fmaf(A0.y, xj.x, av[1].x);  av[1].y  = fmaf(A0.y, xj.y, av[1].y);
            av[2].x  = fmaf(A0.z, xj.x, av[2].x);  av[2].y  = fmaf(A0.z, xj.y, av[2].y);
            av[3].x  = fmaf(A0.w, xj.x, av[3].x);  av[3].y  = fmaf(A0.w, xj.y, av[3].y);
            av[4].x  = fmaf(A1.x, xj.x, av[4].x);  av[4].y  = fmaf(A1.x, xj.y, av[4].y);
            av[5].x  = fmaf(A1.y, xj.x, av[5].x);  av[5].y  = fmaf(A1.y, xj.y, av[5].y);
            av[6].x  = fmaf(A1.z, xj.x, av[6].x);  av[6].y  = fmaf(A1.z, xj.y, av[6].y);
            av[7].x  = fmaf(A1.w, xj.x, av[7].x);  av[7].y  = fmaf(A1.w, xj.y, av[7].y);
            av[8].x  = fmaf(A2.x, xj.x, av[8].x);  av[8].y  = fmaf(A2.x, xj.y, av[8].y);
            av[9].x  = fmaf(A2.y, xj.x, av[9].x);  av[9].y  = fmaf(A2.y, xj.y, av[9].y);
            av[10].x = fmaf(A2.z, xj.x, av[10].x); av[10].y = fmaf(A2.z, xj.y, av[10].y);
            av[11].x = fmaf(A2.w, xj.x, av[11].x); av[11].y = fmaf(A2.w, xj.y, av[11].y);
            av[12].x = fmaf(A3.x, xj.x, av[12].x); av[12].y = fmaf(A3.x, xj.y, av[12].y);
            av[13].x = fmaf(A3.y, xj.x, av[13].x); av[13].y = fmaf(A3.y, xj.y, av[13].y);
            av[14].x = fmaf(A3.z, xj.x, av[14].x); av[14].y = fmaf(A3.z, xj.y, av[14].y);
        }
        #pragma unroll
        for (int i = 0; i < SEQ; i++)
            __stcs((float2*)(ob + i * DIM + col), av[i]);
    }
}

// ================= launch =================
extern "C" void kernel_launch(void* const* d_in, const int* in_sizes, int n_in,
                              void* d_out, int out_size) {
    const float* x  = (const float*)d_in[0];
    const float* Wt = (const float*)d_in[1];
    const float* Wx = (const float*)d_in[2];
    const float* bh = (const float*)d_in[3];
    const float* Wa = (const float*)d_in[4];
    const float* ba = (const float*)d_in[5];
    float* out = (float*)d_out;

    cudaFuncSetAttribute(gemm_qk_kernel,
                         cudaFuncAttributeMaxDynamicSharedMemorySize, A_SMEM_BYTES);

    gemm_qk_kernel<<<A_GRID, A_THREADS, A_SMEM_BYTES>>>(x, Wt, Wx, bh);
    attn_kernel<<<B_GRID, B_THREADS>>>(x, Wa, ba, out);
}